// round 16
// baseline (speedup 1.0000x reference)
#include <cuda_runtime.h>
#include <cuda_fp16.h>
#include <cstdint>

// SharedGroupLinearLayer via single-pass fp16 mma.sync, 2 CTAs/SM (R10 base).
// out = x·Wcat^T + EB[tok%16] gated: out = h1' + a0*hd',
//   a0 = sigmoid(x·rwd + ec[tok%16]); EB1 = e·W1^T+b1, EBd = e·Wd^T+bd.
// Round 16: R10 structure VERBATIM (cp.async staging, 2 barriers/tile, B in
// regs, TILE_M=64, warp 32tok x 32out). EB tables live in SMEM and are loaded
// INSIDE the epilogue (same cost as R10's bias loads); convert loses the emb
// LDS+FADD work. Only +1 persistent register (ec scalar).

#define THREADS 256
#define TILE_M  64
#define NTILES  4096
#define GRID    304

#define RAW_PITCH 320     // 256B row + 64B pad

// dynamic smem offsets
#define RAW_OFF  0        // 2 x 20480B raw x (64 tok x 320B); init: W fp16 tile
#define AB_OFF   40960    // 8KB fp16 A tile (64 tok x 128B)
#define EB1_OFF  49152    // 16x64 f32: e·W1^T + b1
#define EBD_OFF  53248    // 16x64 f32: e·Wd^T + bd
#define RWD_OFF  57344    // 64 f32
#define EC_OFF   57600    // 16 f32: e·rwd
#define A0_OFF   57664    // 64 f32 gate (sigmoid applied)
#define SMEM_TOTAL 57920

__device__ __forceinline__ uint32_t smem_u32(const void* p) {
    uint32_t a;
    asm("{ .reg .u64 t; cvta.to.shared.u64 t, %1; cvt.u32.u64 %0, t; }" : "=r"(a) : "l"(p));
    return a;
}
// pack two f32 -> f16x2 word: low 16 = first arg, high = second
__device__ __forceinline__ uint32_t cvt2h(float lo, float hi) {
    uint32_t r;
    asm("cvt.rn.f16x2.f32 %0, %1, %2;" : "=r"(r) : "f"(hi), "f"(lo));
    return r;
}
__device__ __forceinline__ void ldsm_x4(uint32_t* r, uint32_t addr) {
    asm volatile("ldmatrix.sync.aligned.m8n8.x4.shared.b16 {%0,%1,%2,%3}, [%4];"
        : "=r"(r[0]), "=r"(r[1]), "=r"(r[2]), "=r"(r[3]) : "r"(addr));
}
__device__ __forceinline__ void ldsm_x2(uint32_t* r, uint32_t addr) {
    asm volatile("ldmatrix.sync.aligned.m8n8.x2.shared.b16 {%0,%1}, [%2];"
        : "=r"(r[0]), "=r"(r[1]) : "r"(addr));
}
__device__ __forceinline__ void mma_f16(float* d, const uint32_t* a, const uint32_t* b) {
    asm volatile("mma.sync.aligned.m16n8k16.row.col.f32.f16.f16.f32 "
        "{%0,%1,%2,%3}, {%4,%5,%6,%7}, {%8,%9}, {%0,%1,%2,%3};"
        : "+f"(d[0]), "+f"(d[1]), "+f"(d[2]), "+f"(d[3])
        : "r"(a[0]), "r"(a[1]), "r"(a[2]), "r"(a[3]), "r"(b[0]), "r"(b[1]));
}
__device__ __forceinline__ void cp_async16(uint32_t daddr, const void* gptr) {
    asm volatile("cp.async.ca.shared.global [%0], [%1], 16;" :: "r"(daddr), "l"(gptr));
}
#define CP_COMMIT() asm volatile("cp.async.commit_group;" ::: "memory")
#define CP_WAIT1()  asm volatile("cp.async.wait_group 1;" ::: "memory")

__global__ __launch_bounds__(THREADS, 2)
void sgl_fp16g_kernel(const float* __restrict__ x,
                      const float* __restrict__ emb,
                      const float* __restrict__ read_w,
                      const float* __restrict__ w_stack,
                      const float* __restrict__ b_stack,
                      float* __restrict__ out)
{
    extern __shared__ __align__(1024) char smem[];
    const uint32_t sb = smem_u32(smem);

    const int tid  = threadIdx.x;
    const int lane = tid & 31;
    const int wid  = tid >> 5;
    const int q    = wid & 3;      // n-column group
    const int r    = wid >> 2;     // m-half (tokens r*32..r*32+31)

    float* rwd_s = (float*)(smem + RWD_OFF);
    float* eb1_s = (float*)(smem + EB1_OFF);
    float* ebd_s = (float*)(smem + EBD_OFF);
    float* ec_s  = (float*)(smem + EC_OFF);
    float* a0_s  = (float*)(smem + A0_OFF);

    // ---- one-time setup: rwd first (ec needs it) ----
    for (int i = tid; i < 64; i += THREADS)
        rwd_s[i] = read_w[2 * i] - read_w[2 * i + 1];
    __syncthreads();

    // W fp16 staged in RAW area, column-permuted so thread (q,tc) owns
    // 4 contiguous outputs 16q+4tc..+3. Row n = 128B, XOR-swizzled 16B units.
    for (int i = tid; i < 128 * 32; i += THREADS) {
        int n = i >> 5, kp = (i & 31) * 2;
        int half = n >> 6;              // 0: W1, 1: W0-W1
        int nn = n & 63;
        int p = nn & 7, t = (nn >> 3) & 1;
        int o = (nn & 48) + ((p >> 1) << 2) + 2 * t + (p & 1);
        float v0, v1;
        if (half == 0) {
            v0 = w_stack[4096 + o * 64 + kp];
            v1 = w_stack[4096 + o * 64 + kp + 1];
        } else {
            v0 = w_stack[o * 64 + kp]     - w_stack[4096 + o * 64 + kp];
            v1 = w_stack[o * 64 + kp + 1] - w_stack[4096 + o * 64 + kp + 1];
        }
        int off = n * 128 + (((kp >> 3) ^ (n & 7)) << 4) + (kp & 7) * 2;
        *(uint32_t*)(smem + RAW_OFF + off) = cvt2h(v0, v1);
    }

    // EB tables (true output index o): EB1[nb][o] = e[nb]·W1[o] + b1[o];
    // EBd[nb][o] = e[nb]·(W0-W1)[o] + (b0-b1)[o].  ec[nb] = e[nb]·rwd.
    for (int i = tid; i < 16 * 64; i += THREADS) {
        int nb = i >> 6, o = i & 63;
        const float* ep  = emb + nb * 64;
        const float* w1p = w_stack + 4096 + o * 64;
        const float* w0p = w_stack + o * 64;
        float s1 = 0.f, s0 = 0.f;
        #pragma unroll 8
        for (int k = 0; k < 64; k++) { s1 += ep[k] * w1p[k]; s0 += ep[k] * w0p[k]; }
        float b1 = b_stack[64 + o];
        eb1_s[i] = s1 + b1;
        ebd_s[i] = (s0 - s1) + (b_stack[o] - b1);
    }
    if (tid < 16) {
        const float* ep = emb + tid * 64;
        float s = 0.f;
        #pragma unroll 8
        for (int k = 0; k < 64; k++) s += ep[k] * rwd_s[k];
        ec_s[tid] = s;
    }
    __syncthreads();

    // ---- B fragments -> registers (kept for whole kernel) ----
    uint32_t B[4][4][2];
    #pragma unroll
    for (int nti = 0; nti < 4; nti++) {
        int nt = 2 * q + (nti & 1) + ((nti >> 1) << 3);
        #pragma unroll
        for (int k = 0; k < 4; k++) {
            int row  = nt * 8 + (lane & 7);
            int unit = k * 2 + ((lane >> 3) & 1);
            ldsm_x2(B[nti][k], sb + RAW_OFF + row * 128 + ((unit ^ (row & 7)) << 4));
        }
    }
    __syncthreads();   // RAW area now free for x staging

    const int grp = lane >> 2, tc = lane & 3;
    const int o0  = 16 * q + 4 * tc;
    const int ct  = tid >> 2;        // convert token (0..63)
    const int cp  = tid & 3;         // convert part (4 chunks each)
    const float ecv = ec_s[ct & 15]; // gate constant (1 persistent reg)

    // ---- prologue: stage first tile's x ----
    {
        const float4* src = (const float4*)x + (size_t)blockIdx.x * (TILE_M * 64 / 4);
        #pragma unroll
        for (int k = 0; k < 4; k++) {
            int j = tid + k * THREADS;
            int t = j >> 4, c = j & 15;
            cp_async16(sb + RAW_OFF + t * RAW_PITCH + c * 16, src + j);
        }
    }
    CP_COMMIT();

    int buf = 0;
    for (int tile = blockIdx.x; tile < NTILES; tile += GRID)
    {
        // prefetch next tile into other raw buffer
        {
            int nt = tile + GRID;
            if (nt < NTILES) {
                const float4* src = (const float4*)x + (size_t)nt * (TILE_M * 64 / 4);
                uint32_t dst = sb + RAW_OFF + (buf ^ 1) * 20480;
                #pragma unroll
                for (int k = 0; k < 4; k++) {
                    int j = tid + k * THREADS;
                    int t = j >> 4, c = j & 15;
                    cp_async16(dst + t * RAW_PITCH + c * 16, src + j);
                }
            }
        }
        CP_COMMIT();
        CP_WAIT1();          // current tile's copy complete
        __syncthreads();     // + separates prev MMA reads from A rewrite

        // ---- convert: 4 threads/token, gate + fp16 pack (no emb work) ----
        {
            const char* rawb = smem + RAW_OFF + buf * 20480 + ct * RAW_PITCH;
            float g = 0.f;
            uint2 hw[4];
            #pragma unroll
            for (int i = 0; i < 4; i++) {
                int c = cp + 4 * i;
                float4 v = *(const float4*)(rawb + c * 16);
                const float* rp = &rwd_s[c * 4];
                g += v.x * rp[0] + v.y * rp[1] + v.z * rp[2] + v.w * rp[3];
                hw[i].x = cvt2h(v.x, v.y);
                hw[i].y = cvt2h(v.z, v.w);
            }
            g += __shfl_xor_sync(0xffffffffu, g, 1);
            g += __shfl_xor_sync(0xffffffffu, g, 2);
            if (cp == 0) a0_s[ct] = 1.f / (1.f + __expf(-(g + ecv)));
            #pragma unroll
            for (int i = 0; i < 4; i++) {
                int c = cp + 4 * i;
                uint32_t off = (uint32_t)(ct * 128 + (((c >> 1) ^ (ct & 7)) << 4) + (c & 1) * 8);
                *(uint2*)(smem + AB_OFF + off) = hw[i];
            }
        }
        __syncthreads();

        // ---- MMA: single fp16 pass, B in registers (identical to R10) ----
        float acc[2][4][4];
        #pragma unroll
        for (int m = 0; m < 2; m++)
            #pragma unroll
            for (int n = 0; n < 4; n++) {
                acc[m][n][0] = 0.f; acc[m][n][1] = 0.f;
                acc[m][n][2] = 0.f; acc[m][n][3] = 0.f;
            }

        #pragma unroll
        for (int k = 0; k < 4; k++) {
            #pragma unroll
            for (int m = 0; m < 2; m++) {
                int tok  = r * 32 + m * 16 + (lane & 15);
                int unit = k * 2 + (lane >> 4);
                uint32_t aaddr = sb + AB_OFF + tok * 128 + ((unit ^ (tok & 7)) << 4);
                uint32_t A[4];
                ldsm_x4(A, aaddr);
                mma_f16(acc[m][0], A, B[0][k]);
                mma_f16(acc[m][1], A, B[1][k]);
                mma_f16(acc[m][2], A, B[2][k]);
                mma_f16(acc[m][3], A, B[3][k]);
            }
        }

        // ---- epilogue: EB fold + gate combine + STG.128 (EB loaded HERE,
        //      inside the epilogue, exactly like R10's bias loads) ----
        {
            float* outb = out + (size_t)tile * (TILE_M * 64);
            // token%16 of t0 is grp; of t1 is grp+8 (r*32, m*16 are 0 mod 16)
            float4 e1a = *(const float4*)&eb1_s[grp * 64 + o0];
            float4 eda = *(const float4*)&ebd_s[grp * 64 + o0];
            float4 e1b = *(const float4*)&eb1_s[(grp + 8) * 64 + o0];
            float4 edb = *(const float4*)&ebd_s[(grp + 8) * 64 + o0];
            #pragma unroll
            for (int m = 0; m < 2; m++) {
                int t0 = r * 32 + m * 16 + grp;
                int t1 = t0 + 8;
                float a00 = a0_s[t0];
                float a01 = a0_s[t1];
                float4 w;
                w.x = fmaf(a00, acc[m][2][0] + eda.x, acc[m][0][0] + e1a.x);
                w.y = fmaf(a00, acc[m][2][1] + eda.y, acc[m][0][1] + e1a.y);
                w.z = fmaf(a00, acc[m][3][0] + eda.z, acc[m][1][0] + e1a.z);
                w.w = fmaf(a00, acc[m][3][1] + eda.w, acc[m][1][1] + e1a.w);
                *(float4*)&outb[t0 * 64 + o0] = w;
                w.x = fmaf(a01, acc[m][2][2] + edb.x, acc[m][0][2] + e1b.x);
                w.y = fmaf(a01, acc[m][2][3] + edb.y, acc[m][0][3] + e1b.y);
                w.z = fmaf(a01, acc[m][3][2] + edb.z, acc[m][1][2] + e1b.z);
                w.w = fmaf(a01, acc[m][3][3] + edb.w, acc[m][1][3] + e1b.w);
                *(float4*)&outb[t1 * 64 + o0] = w;
            }
        }
        buf ^= 1;
        // next iteration's top __syncthreads separates this MMA/epilogue
        // from the next convert's A-tile rewrite.
    }
}

extern "C" void kernel_launch(void* const* d_in, const int* in_sizes, int n_in,
                              void* d_out, int out_size)
{
    const float* x       = (const float*)d_in[0];
    const float* emb     = (const float*)d_in[1];
    const float* read_w  = (const float*)d_in[2];
    const float* w_stack = (const float*)d_in[3];
    const float* b_stack = (const float*)d_in[4];
    float* out = (float*)d_out;

    cudaFuncSetAttribute(sgl_fp16g_kernel, cudaFuncAttributeMaxDynamicSharedMemorySize, SMEM_TOTAL);
    sgl_fp16g_kernel<<<GRID, THREADS, SMEM_TOTAL>>>(x, emb, read_w, w_stack, b_stack, out);
}

// round 17
// speedup vs baseline: 4.1978x; 4.1978x over previous
#include <cuda_runtime.h>
#include <cuda_fp16.h>
#include <cstdint>

// SharedGroupLinearLayer via single-pass fp16 mma.sync, 2 CTAs/SM.
// out = (x·W1^T + b1) + a0 * (x·(W0-W1)^T + (b0-b1)), a0 = sigmoid(x·(rw0-rw1))
// Round 17: Round-10 winner VERBATIM (cp.async double-buffered raw staging,
// 2 barriers/tile, B fragments register-resident, TILE_M=64, warp 32tok x
// 32out) with ONE micro-opt: sigmoid computed once per token in convert
// (64/CTA/tile) instead of 4x per thread in the epilogue (1024/CTA/tile).

#define THREADS 256
#define TILE_M  64
#define NTILES  4096
#define GRID    304

#define RAW_PITCH 320     // 256B row + 64B pad

// dynamic smem offsets
#define RAW_OFF  0        // 2 x 20480B raw x (64 tok x 320B); init: W fp16 tile
#define AB_OFF   40960    // 8KB fp16 A tile (64 tok x 128B)
#define EMB_OFF  49152    // 16 x 320B f32 (padded pitch)
#define RWD_OFF  54272    // 64 f32
#define B1_OFF   54528    // 64 f32
#define BD_OFF   54784    // 64 f32
#define A0_OFF   55040    // 64 f32 gate values (sigmoid applied)
#define SMEM_TOTAL 55296

__device__ __forceinline__ uint32_t smem_u32(const void* p) {
    uint32_t a;
    asm("{ .reg .u64 t; cvta.to.shared.u64 t, %1; cvt.u32.u64 %0, t; }" : "=r"(a) : "l"(p));
    return a;
}
// pack two f32 -> f16x2 word: low 16 = first arg, high = second
__device__ __forceinline__ uint32_t cvt2h(float lo, float hi) {
    uint32_t r;
    asm("cvt.rn.f16x2.f32 %0, %1, %2;" : "=r"(r) : "f"(hi), "f"(lo));
    return r;
}
__device__ __forceinline__ void ldsm_x4(uint32_t* r, uint32_t addr) {
    asm volatile("ldmatrix.sync.aligned.m8n8.x4.shared.b16 {%0,%1,%2,%3}, [%4];"
        : "=r"(r[0]), "=r"(r[1]), "=r"(r[2]), "=r"(r[3]) : "r"(addr));
}
__device__ __forceinline__ void ldsm_x2(uint32_t* r, uint32_t addr) {
    asm volatile("ldmatrix.sync.aligned.m8n8.x2.shared.b16 {%0,%1}, [%2];"
        : "=r"(r[0]), "=r"(r[1]) : "r"(addr));
}
__device__ __forceinline__ void mma_f16(float* d, const uint32_t* a, const uint32_t* b) {
    asm volatile("mma.sync.aligned.m16n8k16.row.col.f32.f16.f16.f32 "
        "{%0,%1,%2,%3}, {%4,%5,%6,%7}, {%8,%9}, {%0,%1,%2,%3};"
        : "+f"(d[0]), "+f"(d[1]), "+f"(d[2]), "+f"(d[3])
        : "r"(a[0]), "r"(a[1]), "r"(a[2]), "r"(a[3]), "r"(b[0]), "r"(b[1]));
}
__device__ __forceinline__ void cp_async16(uint32_t daddr, const void* gptr) {
    asm volatile("cp.async.ca.shared.global [%0], [%1], 16;" :: "r"(daddr), "l"(gptr));
}
#define CP_COMMIT() asm volatile("cp.async.commit_group;" ::: "memory")
#define CP_WAIT1()  asm volatile("cp.async.wait_group 1;" ::: "memory")

__global__ __launch_bounds__(THREADS, 2)
void sgl_fp16h_kernel(const float* __restrict__ x,
                      const float* __restrict__ emb,
                      const float* __restrict__ read_w,
                      const float* __restrict__ w_stack,
                      const float* __restrict__ b_stack,
                      float* __restrict__ out)
{
    extern __shared__ __align__(1024) char smem[];
    const uint32_t sb = smem_u32(smem);

    const int tid  = threadIdx.x;
    const int lane = tid & 31;
    const int wid  = tid >> 5;
    const int q    = wid & 3;      // n-column group
    const int r    = wid >> 2;     // m-half (tokens r*32..r*32+31)

    float* emb_s = (float*)(smem + EMB_OFF);   // 320B pitch (80 floats/row)
    float* rwd_s = (float*)(smem + RWD_OFF);
    float* b1_s  = (float*)(smem + B1_OFF);
    float* bd_s  = (float*)(smem + BD_OFF);
    float* a0_s  = (float*)(smem + A0_OFF);

    // ---- one-time setup ----
    for (int i = tid; i < 64; i += THREADS) {
        rwd_s[i] = read_w[2 * i] - read_w[2 * i + 1];
        float b1 = b_stack[64 + i];
        b1_s[i] = b1;
        bd_s[i] = b_stack[i] - b1;
    }
    for (int i = tid; i < 16 * 64; i += THREADS) {
        int row = i >> 6, k = i & 63;
        emb_s[row * 80 + k] = emb[i];
    }

    // Wcat fp16 staged in RAW area, column-permuted so thread (q,tc) owns
    // 4 contiguous outputs 16q+4tc..+3. Row n = 128B, XOR-swizzled 16B units.
    for (int i = tid; i < 128 * 32; i += THREADS) {
        int n = i >> 5, kp = (i & 31) * 2;
        int half = n >> 6;              // 0: W1, 1: W0-W1
        int nn = n & 63;
        int p = nn & 7, t = (nn >> 3) & 1;
        int o = (nn & 48) + ((p >> 1) << 2) + 2 * t + (p & 1);
        float v0, v1;
        if (half == 0) {
            v0 = w_stack[4096 + o * 64 + kp];
            v1 = w_stack[4096 + o * 64 + kp + 1];
        } else {
            v0 = w_stack[o * 64 + kp]     - w_stack[4096 + o * 64 + kp];
            v1 = w_stack[o * 64 + kp + 1] - w_stack[4096 + o * 64 + kp + 1];
        }
        int off = n * 128 + (((kp >> 3) ^ (n & 7)) << 4) + (kp & 7) * 2;
        *(uint32_t*)(smem + RAW_OFF + off) = cvt2h(v0, v1);
    }
    __syncthreads();

    // ---- B fragments -> registers (kept for whole kernel) ----
    // nti 0,1 = h1 tiles (2q, 2q+1); nti 2,3 = hd tiles (2q+8, 2q+9)
    uint32_t Bh[4][4][2];
    #pragma unroll
    for (int nti = 0; nti < 4; nti++) {
        int nt = 2 * q + (nti & 1) + ((nti >> 1) << 3);
        #pragma unroll
        for (int k = 0; k < 4; k++) {
            int row  = nt * 8 + (lane & 7);
            int unit = k * 2 + ((lane >> 3) & 1);
            ldsm_x2(Bh[nti][k], sb + RAW_OFF + row * 128 + ((unit ^ (row & 7)) << 4));
        }
    }
    __syncthreads();   // RAW area now free for x staging

    const int grp = lane >> 2, tc = lane & 3;
    const int o0  = 16 * q + 4 * tc;
    const int ct  = tid >> 2;        // convert token (0..63)
    const int cp  = tid & 3;         // convert part (4 chunks each)

    // ---- prologue: stage first tile's x ----
    {
        const float4* src = (const float4*)x + (size_t)blockIdx.x * (TILE_M * 64 / 4);
        #pragma unroll
        for (int k = 0; k < 4; k++) {
            int j = tid + k * THREADS;
            int t = j >> 4, c = j & 15;
            cp_async16(sb + RAW_OFF + t * RAW_PITCH + c * 16, src + j);
        }
    }
    CP_COMMIT();

    int buf = 0;
    for (int tile = blockIdx.x; tile < NTILES; tile += GRID)
    {
        // prefetch next tile into other raw buffer
        {
            int nt = tile + GRID;
            if (nt < NTILES) {
                const float4* src = (const float4*)x + (size_t)nt * (TILE_M * 64 / 4);
                uint32_t dst = sb + RAW_OFF + (buf ^ 1) * 20480;
                #pragma unroll
                for (int k = 0; k < 4; k++) {
                    int j = tid + k * THREADS;
                    int t = j >> 4, c = j & 15;
                    cp_async16(dst + t * RAW_PITCH + c * 16, src + j);
                }
            }
        }
        CP_COMMIT();
        CP_WAIT1();          // current tile's copy complete
        __syncthreads();     // + separates prev MMA reads from A rewrite

        // ---- convert: 4 threads/token, gate (sigmoid here), fp16 pack ----
        {
            const char* rawb = smem + RAW_OFF + buf * 20480 + ct * RAW_PITCH;
            const float* ep  = &emb_s[(ct & 15) * 80];
            float g = 0.f;
            uint2 hw[4];
            #pragma unroll
            for (int i = 0; i < 4; i++) {
                int c = cp + 4 * i;
                float4 v = *(const float4*)(rawb + c * 16);
                float4 e = *(const float4*)(ep + c * 4);
                v.x += e.x; v.y += e.y; v.z += e.z; v.w += e.w;
                const float* rp = &rwd_s[c * 4];
                g += v.x * rp[0] + v.y * rp[1] + v.z * rp[2] + v.w * rp[3];
                hw[i].x = cvt2h(v.x, v.y);
                hw[i].y = cvt2h(v.z, v.w);
            }
            g += __shfl_xor_sync(0xffffffffu, g, 1);
            g += __shfl_xor_sync(0xffffffffu, g, 2);
            if (cp == 0) a0_s[ct] = 1.f / (1.f + __expf(-g));
            #pragma unroll
            for (int i = 0; i < 4; i++) {
                int c = cp + 4 * i;
                uint32_t off = (uint32_t)(ct * 128 + (((c >> 1) ^ (ct & 7)) << 4) + (c & 1) * 8);
                *(uint2*)(smem + AB_OFF + off) = hw[i];
            }
        }
        __syncthreads();

        // ---- MMA: single fp16 pass, B in registers ----
        float acc[2][4][4];
        #pragma unroll
        for (int m = 0; m < 2; m++)
            #pragma unroll
            for (int n = 0; n < 4; n++) {
                acc[m][n][0] = 0.f; acc[m][n][1] = 0.f;
                acc[m][n][2] = 0.f; acc[m][n][3] = 0.f;
            }

        #pragma unroll
        for (int k = 0; k < 4; k++) {
            #pragma unroll
            for (int m = 0; m < 2; m++) {
                int tok  = r * 32 + m * 16 + (lane & 15);
                int unit = k * 2 + (lane >> 4);
                uint32_t aaddr = sb + AB_OFF + tok * 128 + ((unit ^ (tok & 7)) << 4);
                uint32_t A[4];
                ldsm_x4(A, aaddr);
                mma_f16(acc[m][0], A, Bh[0][k]);
                mma_f16(acc[m][1], A, Bh[1][k]);
                mma_f16(acc[m][2], A, Bh[2][k]);
                mma_f16(acc[m][3], A, Bh[3][k]);
            }
        }

        // ---- epilogue: gate combine (a0 precomputed) + bias + STG.128 ----
        {
            float* outb = out + (size_t)tile * (TILE_M * 64);
            float4 b1v = *(const float4*)&b1_s[o0];
            float4 bdv = *(const float4*)&bd_s[o0];
            #pragma unroll
            for (int m = 0; m < 2; m++) {
                int t0 = r * 32 + m * 16 + grp;
                int t1 = t0 + 8;
                float a00 = a0_s[t0];
                float a01 = a0_s[t1];
                float4 w;
                w.x = fmaf(a00, acc[m][2][0] + bdv.x, acc[m][0][0] + b1v.x);
                w.y = fmaf(a00, acc[m][2][1] + bdv.y, acc[m][0][1] + b1v.y);
                w.z = fmaf(a00, acc[m][3][0] + bdv.z, acc[m][1][0] + b1v.z);
                w.w = fmaf(a00, acc[m][3][1] + bdv.w, acc[m][1][1] + b1v.w);
                *(float4*)&outb[t0 * 64 + o0] = w;
                w.x = fmaf(a01, acc[m][2][2] + bdv.x, acc[m][0][2] + b1v.x);
                w.y = fmaf(a01, acc[m][2][3] + bdv.y, acc[m][0][3] + b1v.y);
                w.z = fmaf(a01, acc[m][3][2] + bdv.z, acc[m][1][2] + b1v.z);
                w.w = fmaf(a01, acc[m][3][3] + bdv.w, acc[m][1][3] + b1v.w);
                *(float4*)&outb[t1 * 64 + o0] = w;
            }
        }
        buf ^= 1;
        // next iteration's top __syncthreads separates this MMA/epilogue
        // from the next convert's A-tile rewrite.
    }
}

extern "C" void kernel_launch(void* const* d_in, const int* in_sizes, int n_in,
                              void* d_out, int out_size)
{
    const float* x       = (const float*)d_in[0];
    const float* emb     = (const float*)d_in[1];
    const float* read_w  = (const float*)d_in[2];
    const float* w_stack = (const float*)d_in[3];
    const float* b_stack = (const float*)d_in[4];
    float* out = (float*)d_out;

    cudaFuncSetAttribute(sgl_fp16h_kernel, cudaFuncAttributeMaxDynamicSharedMemorySize, SMEM_TOTAL);
    sgl_fp16h_kernel<<<GRID, THREADS, SMEM_TOTAL>>>(x, emb, read_w, w_stack, b_stack, out);
}